// round 6
// baseline (speedup 1.0000x reference)
#include <cuda_runtime.h>
#include <cuda_fp16.h>
#include <math.h>
#include <stdint.h>

#define DIM 64
#define TM 128
#define TN 128
#define T_STRIDE 36   // uint32 words per tile row (32 data words + 4 pad)

// ---------------------------------------------------------------------------
// fp16 helpers
// ---------------------------------------------------------------------------
__device__ __forceinline__ uint32_t packh2(float lo, float hi) {
    __half2 h = __floats2half2_rn(lo, hi);
    return *reinterpret_cast<uint32_t*>(&h);
}

__device__ __forceinline__ void mma_f16(float c[4], const uint32_t a[4],
                                        const uint32_t b0, const uint32_t b1) {
    asm volatile(
        "mma.sync.aligned.m16n8k16.row.col.f32.f16.f16.f32 "
        "{%0,%1,%2,%3}, {%4,%5,%6,%7}, {%8,%9}, {%0,%1,%2,%3};"
        : "+f"(c[0]), "+f"(c[1]), "+f"(c[2]), "+f"(c[3])
        : "r"(a[0]), "r"(a[1]), "r"(a[2]), "r"(a[3]), "r"(b0), "r"(b1));
}

__device__ __forceinline__ void ldsm_x4(uint32_t& r0, uint32_t& r1,
                                        uint32_t& r2, uint32_t& r3,
                                        uint32_t addr) {
    asm volatile("ldmatrix.sync.aligned.m8n8.x4.shared.b16 {%0,%1,%2,%3}, [%4];"
                 : "=r"(r0), "=r"(r1), "=r"(r2), "=r"(r3) : "r"(addr));
}

// ---------------------------------------------------------------------------
// Single fused kernel: norms + fp16 mma GEMM + sqrt epilogue.
// CTA: 128x128 tile, 256 threads = 8 warps (2m x 4n), warp tile 64x32.
// B columns are PERMUTED in smem (per 16-col group: physical p=4t+s ->
// tile=s>=2, col=2t+(s&1)) so each thread's epilogue quad is 4 contiguous
// output columns -> STG.128.
//   out[b,j] = sqrt(max(x2[b] + w2[j] - 2*dot, 1e-12))
// ---------------------------------------------------------------------------
__global__ __launch_bounds__(256, 2) void dist_mma_kernel(
    const float* __restrict__ x, const float* __restrict__ w,
    float* __restrict__ out, int B, int K)
{
    __shared__ uint32_t As[128 * T_STRIDE];   // A[m][k] f16 pairs
    __shared__ uint32_t Bs[128 * T_STRIDE];   // B[L][k] f16 pairs (permuted cols)
    __shared__ float x2p[2][128];             // x2 partials (half-row each)
    __shared__ float w2p[2][128];             // w2 partials (k-half each), physical col

    const int tid = threadIdx.x;
    const int lane = tid & 31;
    const int wid = tid >> 5;
    const int warp_m = wid >> 2;      // 0..1
    const int warp_n = wid & 3;       // 0..3
    const int m0 = blockIdx.y * TM;
    const int j0 = blockIdx.x * TN;

    // ---- A tile fill + x2 partials: each thread owns half a row (32 floats)
    {
        int r = tid >> 1;             // 0..127
        int h = tid & 1;              // half
        const float4* xr = reinterpret_cast<const float4*>(x + (long)(m0 + r) * DIM) + h * 8;
        float s = 0.0f;
#pragma unroll
        for (int c = 0; c < 8; c++) {
            float4 v = xr[c];
            s += v.x * v.x + v.y * v.y + v.z * v.z + v.w * v.w;
            *reinterpret_cast<uint2*>(&As[r * T_STRIDE + h * 16 + c * 2]) =
                make_uint2(packh2(v.x, v.y), packh2(v.z, v.w));
        }
        x2p[h][r] = s;
    }

    // ---- B tile fill (transposed + column-permuted) + w2 partials ----
    {
        int n = tid & 127;            // physical column within tile
        int khalf = tid >> 7;         // 0/1 -> k base 0/32
        int kh = khalf * 32;
        // logical storage row L for physical column n
        int grp = n >> 4, p = n & 15;
        int tq = p >> 2, s4 = p & 3;
        int L = grp * 16 + (s4 >> 1) * 8 + tq * 2 + (s4 & 1);

        int j = j0 + n;
        bool inb = (j < K);
        const float* wp = w + j;
        float s = 0.0f;
#pragma unroll
        for (int i = 0; i < 16; i++) {
            int d0 = kh + 2 * i;
            float f0 = inb ? wp[(long)d0 * K] : 0.0f;
            float f1 = inb ? wp[(long)(d0 + 1) * K] : 0.0f;
            s += f0 * f0 + f1 * f1;
            Bs[L * T_STRIDE + (kh >> 1) + i] = packh2(f0, f1);
        }
        w2p[khalf][n] = s;
    }

    __syncthreads();

    // ---- MMA mainloop: 4 k-steps, ldmatrix fragment loads ----
    float acc[4][4][4];
#pragma unroll
    for (int mt = 0; mt < 4; mt++)
#pragma unroll
        for (int nt = 0; nt < 4; nt++)
#pragma unroll
            for (int q = 0; q < 4; q++) acc[mt][nt][q] = 0.0f;

    const int g = lane >> 2;     // group 0..7
    const int t = lane & 3;      // thread-in-group 0..3

    // per-lane ldmatrix base addresses (bytes)
    uint32_t As_base = (uint32_t)__cvta_generic_to_shared(As);
    uint32_t Bs_base = (uint32_t)__cvta_generic_to_shared(Bs);
    // A: matrix rows = m; lane -> row (lane&15), k-offset (lane>>4)*16B
    uint32_t addrA = As_base
        + (uint32_t)((warp_m * 64 + (lane & 15)) * T_STRIDE * 4)
        + ((lane >> 4) << 4);
    // B: matrix rows = logical n; lane -> row (lane&7) + 8*(lane>=16),
    //    k-offset ((lane>>3)&1)*16B
    uint32_t addrB = Bs_base
        + (uint32_t)((warp_n * 32 + (lane & 7) + ((lane >> 4) << 3)) * T_STRIDE * 4)
        + (((lane >> 3) & 1) << 4);

#pragma unroll
    for (int ks = 0; ks < 4; ks++) {
        uint32_t a[4][4];
#pragma unroll
        for (int mt = 0; mt < 4; mt++)
            ldsm_x4(a[mt][0], a[mt][1], a[mt][2], a[mt][3],
                    addrA + mt * (16 * T_STRIDE * 4) + ks * 32);

        uint32_t b[2][4];   // [ntp] -> {tile0.b0, tile0.b1, tile1.b0, tile1.b1}
#pragma unroll
        for (int ntp = 0; ntp < 2; ntp++)
            ldsm_x4(b[ntp][0], b[ntp][1], b[ntp][2], b[ntp][3],
                    addrB + ntp * (16 * T_STRIDE * 4) + ks * 32);

#pragma unroll
        for (int mt = 0; mt < 4; mt++)
#pragma unroll
            for (int ntp = 0; ntp < 2; ntp++) {
                mma_f16(acc[mt][2 * ntp + 0], a[mt], b[ntp][0], b[ntp][1]);
                mma_f16(acc[mt][2 * ntp + 1], a[mt], b[ntp][2], b[ntp][3]);
            }
    }

    // ---- Epilogue: combine norm partials, sqrt, STG.128 ----
    float x2lo[4], x2hi[4];
#pragma unroll
    for (int mt = 0; mt < 4; mt++) {
        int R = warp_m * 64 + mt * 16 + g;
        x2lo[mt] = x2p[0][R] + x2p[1][R];
        x2hi[mt] = x2p[0][R + 8] + x2p[1][R + 8];
    }
    float w2v[2][4];
#pragma unroll
    for (int ntp = 0; ntp < 2; ntp++)
#pragma unroll
        for (int q = 0; q < 4; q++) {
            int col = warp_n * 32 + ntp * 16 + 4 * t + q;
            w2v[ntp][q] = w2p[0][col] + w2p[1][col];
        }

#pragma unroll
    for (int mt = 0; mt < 4; mt++) {
        int R = warp_m * 64 + mt * 16 + g;
        long row0 = (long)(m0 + R) * K;
        long row1 = (long)(m0 + R + 8) * K;
#pragma unroll
        for (int ntp = 0; ntp < 2; ntp++) {
            int j = j0 + warp_n * 32 + ntp * 16 + 4 * t;
            const float* aq0 = acc[mt][2 * ntp + 0];
            const float* aq1 = acc[mt][2 * ntp + 1];
            float4 lo, hi;
            lo.x = sqrtf(fmaxf(x2lo[mt] + w2v[ntp][0] - 2.0f * aq0[0], 1e-12f));
            lo.y = sqrtf(fmaxf(x2lo[mt] + w2v[ntp][1] - 2.0f * aq0[1], 1e-12f));
            lo.z = sqrtf(fmaxf(x2lo[mt] + w2v[ntp][2] - 2.0f * aq1[0], 1e-12f));
            lo.w = sqrtf(fmaxf(x2lo[mt] + w2v[ntp][3] - 2.0f * aq1[1], 1e-12f));
            hi.x = sqrtf(fmaxf(x2hi[mt] + w2v[ntp][0] - 2.0f * aq0[2], 1e-12f));
            hi.y = sqrtf(fmaxf(x2hi[mt] + w2v[ntp][1] - 2.0f * aq0[3], 1e-12f));
            hi.z = sqrtf(fmaxf(x2hi[mt] + w2v[ntp][2] - 2.0f * aq1[2], 1e-12f));
            hi.w = sqrtf(fmaxf(x2hi[mt] + w2v[ntp][3] - 2.0f * aq1[3], 1e-12f));
            if (j + 4 <= K) {
                *reinterpret_cast<float4*>(out + row0 + j) = lo;
                *reinterpret_cast<float4*>(out + row1 + j) = hi;
            } else {
                float lov[4] = {lo.x, lo.y, lo.z, lo.w};
                float hiv[4] = {hi.x, hi.y, hi.z, hi.w};
                for (int q = 0; q < 4; q++) {
                    if (j + q < K) {
                        out[row0 + j + q] = lov[q];
                        out[row1 + j + q] = hiv[q];
                    }
                }
            }
        }
    }
}

// ---------------------------------------------------------------------------
// Launch (single kernel)
// ---------------------------------------------------------------------------
extern "C" void kernel_launch(void* const* d_in, const int* in_sizes, int n_in,
                              void* d_out, int out_size) {
    const float* x = (const float*)d_in[0];   // [B, 64]
    const float* w = (const float*)d_in[1];   // [64, K]
    float* out = (float*)d_out;               // [B, K]

    int B = in_sizes[0] / DIM;
    int K = in_sizes[1] / DIM;

    dim3 grid((K + TN - 1) / TN, (B + TM - 1) / TM);
    dist_mma_kernel<<<grid, 256>>>(x, w, out, B, K);
}

// round 7
// speedup vs baseline: 1.1923x; 1.1923x over previous
#include <cuda_runtime.h>
#include <cuda_fp16.h>
#include <math.h>
#include <stdint.h>

#define DIM 64
#define TM 128
#define TN 128

// ---------------------------------------------------------------------------
// fp16 helpers
// ---------------------------------------------------------------------------
__device__ __forceinline__ uint32_t packh2(float lo, float hi) {
    __half2 h = __floats2half2_rn(lo, hi);
    return *reinterpret_cast<uint32_t*>(&h);
}

__device__ __forceinline__ void mma_f16(float c[4], const uint32_t a[4],
                                        const uint32_t b0, const uint32_t b1) {
    asm volatile(
        "mma.sync.aligned.m16n8k16.row.col.f32.f16.f16.f32 "
        "{%0,%1,%2,%3}, {%4,%5,%6,%7}, {%8,%9}, {%0,%1,%2,%3};"
        : "+f"(c[0]), "+f"(c[1]), "+f"(c[2]), "+f"(c[3])
        : "r"(a[0]), "r"(a[1]), "r"(a[2]), "r"(a[3]), "r"(b0), "r"(b1));
}

__device__ __forceinline__ void ldsm_x4(uint32_t& r0, uint32_t& r1,
                                        uint32_t& r2, uint32_t& r3,
                                        uint32_t addr) {
    asm volatile("ldmatrix.sync.aligned.m8n8.x4.shared.b16 {%0,%1,%2,%3}, [%4];"
                 : "=r"(r0), "=r"(r1), "=r"(r2), "=r"(r3) : "r"(addr));
}

// ---------------------------------------------------------------------------
// Single fused kernel: norms + fp16 mma GEMM + sqrt epilogue.
// CTA: 128x128 tile, 256 threads = 8 warps (2m x 4n), warp tile 64x32.
// Tiles stored SW128-swizzled, 128B rows (32 words, no padding):
//   word(row, k16unit u) = row*32 + ((u ^ (row&7)) << 2)   (+ within-unit)
// B columns PERMUTED (per 16-col group: physical p=4t+s -> tile s>=2,
// col 2t+(s&1)) so each thread's epilogue quad = 4 contiguous columns.
//   out[b,j] = sqrt(max(x2[b] + w2[j] - 2*dot, 1e-12))
// ---------------------------------------------------------------------------
__global__ __launch_bounds__(256, 2) void dist_mma_kernel(
    const float* __restrict__ x, const float* __restrict__ w,
    float* __restrict__ out, int B, int K)
{
    __shared__ uint32_t As[128 * 32];   // A[m][k] f16 pairs, SW128
    __shared__ uint32_t Bs[128 * 32];   // B[L][k] f16 pairs, SW128, permuted cols
    __shared__ float x2s[128];
    __shared__ float w2p[2][128];       // w2 partials per k-half, physical col

    const int tid = threadIdx.x;
    const int lane = tid & 31;
    const int wid = tid >> 5;
    const int warp_m = wid >> 2;      // 0..1
    const int warp_n = wid & 3;       // 0..3
    const int m0 = blockIdx.y * TM;
    const int j0 = blockIdx.x * TN;

    // ---- A tile fill (coalesced) + inline x2 via shuffle reduction ----
    {
        const float4* xs = reinterpret_cast<const float4*>(x + (long)m0 * DIM);
#pragma unroll
        for (int i = 0; i < 8; i++) {
            int e = tid + i * 256;       // float4 index, 0..2047
            int r = e >> 4;              // 16 float4 per 64-float row
            int c4 = e & 15;             // == lane & 15
            float4 v = xs[e];
            float s = v.x * v.x + v.y * v.y + v.z * v.z + v.w * v.w;
            s += __shfl_xor_sync(0xffffffffu, s, 1);
            s += __shfl_xor_sync(0xffffffffu, s, 2);
            s += __shfl_xor_sync(0xffffffffu, s, 4);
            s += __shfl_xor_sync(0xffffffffu, s, 8);
            if (c4 == 0) x2s[r] = s;
            // swizzled store: 8 bytes at byte (r*128 + c4*8) ^ ((r&7)<<4)
            int word = r * 32 + ((c4 * 2) ^ ((r & 7) << 2));
            *reinterpret_cast<uint2*>(&As[word]) =
                make_uint2(packh2(v.x, v.y), packh2(v.z, v.w));
        }
    }

    // ---- B tile fill (transposed, permuted, swizzled) + w2 partials ----
    {
        int n = tid & 127;            // physical column within tile
        int khalf = tid >> 7;         // k base 0 / 32
        int grp = n >> 4, p = n & 15;
        int tq = p >> 2, s4 = p & 3;
        int L = grp * 16 + (s4 >> 1) * 8 + tq * 2 + (s4 & 1);   // storage row

        int j = j0 + n;
        bool inb = (j < K);
        const float* wp = w + j;
        float s = 0.0f;
#pragma unroll
        for (int q = 0; q < 4; q++) {
            float f[8];
#pragma unroll
            for (int dd = 0; dd < 8; dd++) {
                int d = khalf * 32 + q * 8 + dd;
                f[dd] = inb ? wp[(long)d * K] : 0.0f;
                s += f[dd] * f[dd];
            }
            uint4 u = make_uint4(packh2(f[0], f[1]), packh2(f[2], f[3]),
                                 packh2(f[4], f[5]), packh2(f[6], f[7]));
            int word = L * 32 + (((khalf * 4 + q) ^ (L & 7)) << 2);
            *reinterpret_cast<uint4*>(&Bs[word]) = u;
        }
        w2p[khalf][n] = s;
    }

    __syncthreads();

    // ---- MMA mainloop: 4 k-steps, ldmatrix fragment loads (swizzled) ----
    float acc[4][4][4];
#pragma unroll
    for (int mt = 0; mt < 4; mt++)
#pragma unroll
        for (int nt = 0; nt < 4; nt++)
#pragma unroll
            for (int q = 0; q < 4; q++) acc[mt][nt][q] = 0.0f;

    const int g = lane >> 2;
    const int t = lane & 3;

    uint32_t As_base = (uint32_t)__cvta_generic_to_shared(As);
    uint32_t Bs_base = (uint32_t)__cvta_generic_to_shared(Bs);

    const int rowA_loc = lane & 15;                       // within 16-row tile
    const int a_klo = lane >> 4;                          // 0/1: +8 halfs
    const int sxA = rowA_loc & 7;
    const int rowB_loc = (lane & 7) + ((lane >> 4) << 3); // within 16-row tile
    const int b_klo = (lane >> 3) & 1;
    const int sxB = rowB_loc & 7;

    // per-mt / per-ntp row byte bases (row*128)
    uint32_t baseA[4], baseB[2];
#pragma unroll
    for (int mt = 0; mt < 4; mt++)
        baseA[mt] = As_base + (uint32_t)((warp_m * 64 + mt * 16 + rowA_loc) << 7);
#pragma unroll
    for (int ntp = 0; ntp < 2; ntp++)
        baseB[ntp] = Bs_base + (uint32_t)((warp_n * 32 + ntp * 16 + rowB_loc) << 7);

#pragma unroll
    for (int ks = 0; ks < 4; ks++) {
        uint32_t colA = (uint32_t)(((2 * ks + a_klo) ^ sxA) << 4);
        uint32_t colB = (uint32_t)(((2 * ks + b_klo) ^ sxB) << 4);

        uint32_t a[4][4];
#pragma unroll
        for (int mt = 0; mt < 4; mt++)
            ldsm_x4(a[mt][0], a[mt][1], a[mt][2], a[mt][3], baseA[mt] + colA);

        uint32_t b[2][4];
#pragma unroll
        for (int ntp = 0; ntp < 2; ntp++)
            ldsm_x4(b[ntp][0], b[ntp][1], b[ntp][2], b[ntp][3], baseB[ntp] + colB);

#pragma unroll
        for (int mt = 0; mt < 4; mt++)
#pragma unroll
            for (int ntp = 0; ntp < 2; ntp++) {
                mma_f16(acc[mt][2 * ntp + 0], a[mt], b[ntp][0], b[ntp][1]);
                mma_f16(acc[mt][2 * ntp + 1], a[mt], b[ntp][2], b[ntp][3]);
            }
    }

    // ---- Epilogue: combine norms, sqrt, STG.128 ----
    float w2v[2][4];
#pragma unroll
    for (int ntp = 0; ntp < 2; ntp++)
#pragma unroll
        for (int q = 0; q < 4; q++) {
            int col = warp_n * 32 + ntp * 16 + 4 * t + q;
            w2v[ntp][q] = w2p[0][col] + w2p[1][col];
        }

#pragma unroll
    for (int mt = 0; mt < 4; mt++) {
        int R = warp_m * 64 + mt * 16 + g;
        float x2lo = x2s[R];
        float x2hi = x2s[R + 8];
        long row0 = (long)(m0 + R) * K;
        long row1 = (long)(m0 + R + 8) * K;
#pragma unroll
        for (int ntp = 0; ntp < 2; ntp++) {
            int j = j0 + warp_n * 32 + ntp * 16 + 4 * t;
            const float* aq0 = acc[mt][2 * ntp + 0];
            const float* aq1 = acc[mt][2 * ntp + 1];
            float4 lo, hi;
            lo.x = sqrtf(fmaxf(x2lo + w2v[ntp][0] - 2.0f * aq0[0], 1e-12f));
            lo.y = sqrtf(fmaxf(x2lo + w2v[ntp][1] - 2.0f * aq0[1], 1e-12f));
            lo.z = sqrtf(fmaxf(x2lo + w2v[ntp][2] - 2.0f * aq1[0], 1e-12f));
            lo.w = sqrtf(fmaxf(x2lo + w2v[ntp][3] - 2.0f * aq1[1], 1e-12f));
            hi.x = sqrtf(fmaxf(x2hi + w2v[ntp][0] - 2.0f * aq0[2], 1e-12f));
            hi.y = sqrtf(fmaxf(x2hi + w2v[ntp][1] - 2.0f * aq0[3], 1e-12f));
            hi.z = sqrtf(fmaxf(x2hi + w2v[ntp][2] - 2.0f * aq1[2], 1e-12f));
            hi.w = sqrtf(fmaxf(x2hi + w2v[ntp][3] - 2.0f * aq1[3], 1e-12f));
            if (j + 4 <= K) {
                *reinterpret_cast<float4*>(out + row0 + j) = lo;
                *reinterpret_cast<float4*>(out + row1 + j) = hi;
            } else {
                float lov[4] = {lo.x, lo.y, lo.z, lo.w};
                float hiv[4] = {hi.x, hi.y, hi.z, hi.w};
                for (int q = 0; q < 4; q++) {
                    if (j + q < K) {
                        out[row0 + j + q] = lov[q];
                        out[row1 + j + q] = hiv[q];
                    }
                }
            }
        }
    }
}

// ---------------------------------------------------------------------------
// Launch (single kernel)
// ---------------------------------------------------------------------------
extern "C" void kernel_launch(void* const* d_in, const int* in_sizes, int n_in,
                              void* d_out, int out_size) {
    const float* x = (const float*)d_in[0];   // [B, 64]
    const float* w = (const float*)d_in[1];   // [64, K]
    float* out = (float*)d_out;               // [B, K]

    int B = in_sizes[0] / DIM;
    int K = in_sizes[1] / DIM;

    dim3 grid((K + TN - 1) / TN, (B + TM - 1) / TM);
    dist_mma_kernel<<<grid, 256>>>(x, w, out, B, K);
}

// round 8
// speedup vs baseline: 1.3483x; 1.1309x over previous
#include <cuda_runtime.h>
#include <cuda_fp16.h>
#include <math.h>
#include <stdint.h>

#define DIM 64
#define TM 128
#define TN 128

// ---------------------------------------------------------------------------
// helpers
// ---------------------------------------------------------------------------
__device__ __forceinline__ uint32_t packh2(float lo, float hi) {
    __half2 h = __floats2half2_rn(lo, hi);
    return *reinterpret_cast<uint32_t*>(&h);
}

__device__ __forceinline__ float sqrt_approx(float v) {
    float r;
    asm("sqrt.approx.f32 %0, %1;" : "=f"(r) : "f"(v));
    return r;
}

__device__ __forceinline__ float dist_val(float s, float a) {
    // sqrt(max(s - 2a, 1e-12)) with 1-instruction MUFU sqrt
    return sqrt_approx(fmaxf(fmaf(-2.0f, a, s), 1e-12f));
}

__device__ __forceinline__ void mma_f16(float c[4], const uint32_t a[4],
                                        const uint32_t b0, const uint32_t b1) {
    asm volatile(
        "mma.sync.aligned.m16n8k16.row.col.f32.f16.f16.f32 "
        "{%0,%1,%2,%3}, {%4,%5,%6,%7}, {%8,%9}, {%0,%1,%2,%3};"
        : "+f"(c[0]), "+f"(c[1]), "+f"(c[2]), "+f"(c[3])
        : "r"(a[0]), "r"(a[1]), "r"(a[2]), "r"(a[3]), "r"(b0), "r"(b1));
}

__device__ __forceinline__ void ldsm_x4(uint32_t& r0, uint32_t& r1,
                                        uint32_t& r2, uint32_t& r3,
                                        uint32_t addr) {
    asm volatile("ldmatrix.sync.aligned.m8n8.x4.shared.b16 {%0,%1,%2,%3}, [%4];"
                 : "=r"(r0), "=r"(r1), "=r"(r2), "=r"(r3) : "r"(addr));
}

// ---------------------------------------------------------------------------
// Single fused kernel: norms + fp16 mma GEMM + sqrt epilogue.
// CTA: 128x128 tile, 256 threads = 8 warps (2m x 4n), warp tile 64x32.
// Tiles SW128-swizzled, 128B rows. B columns PERMUTED (per 16-col group:
// physical p=4t+s -> tile s>=2, col 2t+(s&1)) so each thread's epilogue quad
// is 4 contiguous output columns -> STG.128.
//   out[b,j] = sqrt(max(x2[b] + w2[j] - 2*dot, 1e-12))
// ---------------------------------------------------------------------------
__global__ __launch_bounds__(256, 2) void dist_mma_kernel(
    const float* __restrict__ x, const float* __restrict__ w,
    float* __restrict__ out, int B, int K)
{
    __shared__ uint32_t As[128 * 32];   // A[m][k] f16 pairs, SW128
    __shared__ uint32_t Bs[128 * 32];   // B[L][k] f16 pairs, SW128, permuted cols
    __shared__ float x2s[128];
    __shared__ float w2p[2][128];       // w2 partials per k-half, physical col

    const int tid = threadIdx.x;
    const int lane = tid & 31;
    const int wid = tid >> 5;
    const int warp_m = wid >> 2;      // 0..1
    const int warp_n = wid & 3;       // 0..3
    const int m0 = blockIdx.y * TM;
    const int j0 = blockIdx.x * TN;

    // ---- A tile fill (coalesced) + inline x2 via shuffle reduction ----
    {
        const float4* xs = reinterpret_cast<const float4*>(x + (long)m0 * DIM);
#pragma unroll
        for (int i = 0; i < 8; i++) {
            int e = tid + i * 256;       // float4 index, 0..2047
            int r = e >> 4;              // 16 float4 per 64-float row
            int c4 = e & 15;             // == lane & 15
            float4 v = xs[e];
            float s = v.x * v.x + v.y * v.y + v.z * v.z + v.w * v.w;
            s += __shfl_xor_sync(0xffffffffu, s, 1);
            s += __shfl_xor_sync(0xffffffffu, s, 2);
            s += __shfl_xor_sync(0xffffffffu, s, 4);
            s += __shfl_xor_sync(0xffffffffu, s, 8);
            if (c4 == 0) x2s[r] = s;
            int word = r * 32 + ((c4 * 2) ^ ((r & 7) << 2));
            *reinterpret_cast<uint2*>(&As[word]) =
                make_uint2(packh2(v.x, v.y), packh2(v.z, v.w));
        }
    }

    // ---- B tile fill (transposed, permuted, swizzled) + w2 partials ----
    {
        int n = tid & 127;            // physical column within tile
        int khalf = tid >> 7;         // k base 0 / 32
        int grp = n >> 4, p = n & 15;
        int tq = p >> 2, s4 = p & 3;
        int L = grp * 16 + (s4 >> 1) * 8 + tq * 2 + (s4 & 1);   // storage row

        int j = j0 + n;
        bool inb = (j < K);
        const float* wp = w + j;
        float s = 0.0f;
#pragma unroll
        for (int q = 0; q < 4; q++) {
            float f[8];
#pragma unroll
            for (int dd = 0; dd < 8; dd++) {
                int d = khalf * 32 + q * 8 + dd;
                f[dd] = inb ? wp[(long)d * K] : 0.0f;
                s += f[dd] * f[dd];
            }
            uint4 u = make_uint4(packh2(f[0], f[1]), packh2(f[2], f[3]),
                                 packh2(f[4], f[5]), packh2(f[6], f[7]));
            int word = L * 32 + (((khalf * 4 + q) ^ (L & 7)) << 2);
            *reinterpret_cast<uint4*>(&Bs[word]) = u;
        }
        w2p[khalf][n] = s;
    }

    __syncthreads();

    // ---- MMA mainloop: 4 k-steps, ldmatrix fragment loads (swizzled) ----
    float acc[4][4][4];
#pragma unroll
    for (int mt = 0; mt < 4; mt++)
#pragma unroll
        for (int nt = 0; nt < 4; nt++)
#pragma unroll
            for (int q = 0; q < 4; q++) acc[mt][nt][q] = 0.0f;

    const int g = lane >> 2;
    const int t = lane & 3;

    uint32_t As_base = (uint32_t)__cvta_generic_to_shared(As);
    uint32_t Bs_base = (uint32_t)__cvta_generic_to_shared(Bs);

    const int rowA_loc = lane & 15;
    const int a_klo = lane >> 4;
    const int sxA = rowA_loc & 7;
    const int rowB_loc = (lane & 7) + ((lane >> 4) << 3);
    const int b_klo = (lane >> 3) & 1;
    const int sxB = rowB_loc & 7;

    uint32_t baseA[4], baseB[2];
#pragma unroll
    for (int mt = 0; mt < 4; mt++)
        baseA[mt] = As_base + (uint32_t)((warp_m * 64 + mt * 16 + rowA_loc) << 7);
#pragma unroll
    for (int ntp = 0; ntp < 2; ntp++)
        baseB[ntp] = Bs_base + (uint32_t)((warp_n * 32 + ntp * 16 + rowB_loc) << 7);

#pragma unroll
    for (int ks = 0; ks < 4; ks++) {
        uint32_t colA = (uint32_t)(((2 * ks + a_klo) ^ sxA) << 4);
        uint32_t colB = (uint32_t)(((2 * ks + b_klo) ^ sxB) << 4);

        uint32_t a[4][4];
#pragma unroll
        for (int mt = 0; mt < 4; mt++)
            ldsm_x4(a[mt][0], a[mt][1], a[mt][2], a[mt][3], baseA[mt] + colA);

        uint32_t b[2][4];
#pragma unroll
        for (int ntp = 0; ntp < 2; ntp++)
            ldsm_x4(b[ntp][0], b[ntp][1], b[ntp][2], b[ntp][3], baseB[ntp] + colB);

#pragma unroll
        for (int mt = 0; mt < 4; mt++)
#pragma unroll
            for (int ntp = 0; ntp < 2; ntp++) {
                mma_f16(acc[mt][2 * ntp + 0], a[mt], b[ntp][0], b[ntp][1]);
                mma_f16(acc[mt][2 * ntp + 1], a[mt], b[ntp][2], b[ntp][3]);
            }
    }

    // ---- Epilogue: combine norms, approx-sqrt, STG.128 ----
    float w2v[2][4];
#pragma unroll
    for (int ntp = 0; ntp < 2; ntp++)
#pragma unroll
        for (int q = 0; q < 4; q++) {
            int col = warp_n * 32 + ntp * 16 + 4 * t + q;
            w2v[ntp][q] = w2p[0][col] + w2p[1][col];
        }

#pragma unroll
    for (int mt = 0; mt < 4; mt++) {
        int R = warp_m * 64 + mt * 16 + g;
        float x2lo = x2s[R];
        float x2hi = x2s[R + 8];
        long row0 = (long)(m0 + R) * K;
        long row1 = (long)(m0 + R + 8) * K;
#pragma unroll
        for (int ntp = 0; ntp < 2; ntp++) {
            int j = j0 + warp_n * 32 + ntp * 16 + 4 * t;
            const float* aq0 = acc[mt][2 * ntp + 0];
            const float* aq1 = acc[mt][2 * ntp + 1];
            float4 lo, hi;
            lo.x = dist_val(x2lo + w2v[ntp][0], aq0[0]);
            lo.y = dist_val(x2lo + w2v[ntp][1], aq0[1]);
            lo.z = dist_val(x2lo + w2v[ntp][2], aq1[0]);
            lo.w = dist_val(x2lo + w2v[ntp][3], aq1[1]);
            hi.x = dist_val(x2hi + w2v[ntp][0], aq0[2]);
            hi.y = dist_val(x2hi + w2v[ntp][1], aq0[3]);
            hi.z = dist_val(x2hi + w2v[ntp][2], aq1[2]);
            hi.w = dist_val(x2hi + w2v[ntp][3], aq1[3]);
            if (j + 4 <= K) {
                *reinterpret_cast<float4*>(out + row0 + j) = lo;
                *reinterpret_cast<float4*>(out + row1 + j) = hi;
            } else {
                float lov[4] = {lo.x, lo.y, lo.z, lo.w};
                float hiv[4] = {hi.x, hi.y, hi.z, hi.w};
                for (int q = 0; q < 4; q++) {
                    if (j + q < K) {
                        out[row0 + j + q] = lov[q];
                        out[row1 + j + q] = hiv[q];
                    }
                }
            }
        }
    }
}

// ---------------------------------------------------------------------------
// Launch (single kernel)
// ---------------------------------------------------------------------------
extern "C" void kernel_launch(void* const* d_in, const int* in_sizes, int n_in,
                              void* d_out, int out_size) {
    const float* x = (const float*)d_in[0];   // [B, 64]
    const float* w = (const float*)d_in[1];   // [64, K]
    float* out = (float*)d_out;               // [B, K]

    int B = in_sizes[0] / DIM;
    int K = in_sizes[1] / DIM;

    dim3 grid((K + TN - 1) / TN, (B + TM - 1) / TM);
    dist_mma_kernel<<<grid, 256>>>(x, w, out, B, K);
}

// round 9
// speedup vs baseline: 1.4364x; 1.0653x over previous
#include <cuda_runtime.h>
#include <cuda_fp16.h>
#include <math.h>
#include <stdint.h>

#define DIM 64
#define TM 128
#define TN 128

// ---------------------------------------------------------------------------
// helpers
// ---------------------------------------------------------------------------
__device__ __forceinline__ uint32_t packh2(float lo, float hi) {
    __half2 h = __floats2half2_rn(lo, hi);
    return *reinterpret_cast<uint32_t*>(&h);
}

__device__ __forceinline__ float sqrt_approx(float v) {
    float r;
    asm("sqrt.approx.f32 %0, %1;" : "=f"(r) : "f"(v));
    return r;
}

__device__ __forceinline__ float dist_val(float s, float a) {
    return sqrt_approx(fmaxf(fmaf(-2.0f, a, s), 1e-12f));
}

__device__ __forceinline__ void mma_f16(float c[4], const uint32_t a[4],
                                        const uint32_t b0, const uint32_t b1) {
    asm volatile(
        "mma.sync.aligned.m16n8k16.row.col.f32.f16.f16.f32 "
        "{%0,%1,%2,%3}, {%4,%5,%6,%7}, {%8,%9}, {%0,%1,%2,%3};"
        : "+f"(c[0]), "+f"(c[1]), "+f"(c[2]), "+f"(c[3])
        : "r"(a[0]), "r"(a[1]), "r"(a[2]), "r"(a[3]), "r"(b0), "r"(b1));
}

__device__ __forceinline__ void ldsm_x4(uint32_t& r0, uint32_t& r1,
                                        uint32_t& r2, uint32_t& r3,
                                        uint32_t addr) {
    asm volatile("ldmatrix.sync.aligned.m8n8.x4.shared.b16 {%0,%1,%2,%3}, [%4];"
                 : "=r"(r0), "=r"(r1), "=r"(r2), "=r"(r3) : "r"(addr));
}

// ---------------------------------------------------------------------------
// Single fused kernel: norms + fp16 mma GEMM + sqrt epilogue.
// CTA: 128x128 tile, 256 threads = 8 warps (2m x 4n), warp tile 64x32.
// Tiles SW128-swizzled, 128B rows. B columns PERMUTED (per 16-col group:
// physical p=4t+s -> tile s>=2, col 2t+(s&1)) so each thread's epilogue quad
// is 4 contiguous output columns -> STG.128.
//   out[b,j] = sqrt(max(x2[b] + w2[j] - 2*dot, 1e-12))
// ---------------------------------------------------------------------------
__global__ __launch_bounds__(256, 2) void dist_mma_kernel(
    const float* __restrict__ x, const float* __restrict__ w,
    float* __restrict__ out, int B, int K)
{
    __shared__ uint32_t As[128 * 32];   // A[m][k] f16 pairs, SW128
    __shared__ uint32_t Bs[128 * 32];   // B[L][k] f16 pairs, SW128, permuted cols
    __shared__ float x2s[128];
    __shared__ float w2p[2][128];       // w2 partials per k-half, physical col

    const int tid = threadIdx.x;
    const int lane = tid & 31;
    const int wid = tid >> 5;
    const int warp_m = wid >> 2;      // 0..1
    const int warp_n = wid & 3;       // 0..3
    const int m0 = blockIdx.y * TM;
    const int j0 = blockIdx.x * TN;

    // ---- A tile fill (coalesced) + inline x2 via shuffle reduction ----
    {
        const float4* xs = reinterpret_cast<const float4*>(x + (long)m0 * DIM);
#pragma unroll
        for (int i = 0; i < 8; i++) {
            int e = tid + i * 256;       // float4 index, 0..2047
            int r = e >> 4;              // 16 float4 per 64-float row
            int c4 = e & 15;             // == lane & 15
            float4 v = xs[e];
            float s = v.x * v.x + v.y * v.y + v.z * v.z + v.w * v.w;
            s += __shfl_xor_sync(0xffffffffu, s, 1);
            s += __shfl_xor_sync(0xffffffffu, s, 2);
            s += __shfl_xor_sync(0xffffffffu, s, 4);
            s += __shfl_xor_sync(0xffffffffu, s, 8);
            if (c4 == 0) x2s[r] = s;
            int word = r * 32 + ((c4 * 2) ^ ((r & 7) << 2));
            *reinterpret_cast<uint2*>(&As[word]) =
                make_uint2(packh2(v.x, v.y), packh2(v.z, v.w));
        }
    }

    // ---- B tile fill (transposed, permuted, swizzled) + w2 partials ----
    {
        int n = tid & 127;            // physical column within tile
        int khalf = tid >> 7;         // k base 0 / 32
        int grp = n >> 4, p = n & 15;
        int tq = p >> 2, s4 = p & 3;
        int L = grp * 16 + (s4 >> 1) * 8 + tq * 2 + (s4 & 1);   // storage row

        int j = j0 + n;
        bool inb = (j < K);
        const float* wp = w + j;
        float s = 0.0f;
#pragma unroll
        for (int q = 0; q < 4; q++) {
            float f[8];
#pragma unroll
            for (int dd = 0; dd < 8; dd++) {
                int d = khalf * 32 + q * 8 + dd;
                f[dd] = inb ? wp[(long)d * K] : 0.0f;
                s += f[dd] * f[dd];
            }
            uint4 u = make_uint4(packh2(f[0], f[1]), packh2(f[2], f[3]),
                                 packh2(f[4], f[5]), packh2(f[6], f[7]));
            int word = L * 32 + (((khalf * 4 + q) ^ (L & 7)) << 2);
            *reinterpret_cast<uint4*>(&Bs[word]) = u;
        }
        w2p[khalf][n] = s;
    }

    __syncthreads();

    // ---- MMA mainloop: 4 k-steps; A fragment loaded per-mt (low reg press.)
    float acc[4][4][4];
#pragma unroll
    for (int mt = 0; mt < 4; mt++)
#pragma unroll
        for (int nt = 0; nt < 4; nt++)
#pragma unroll
            for (int q = 0; q < 4; q++) acc[mt][nt][q] = 0.0f;

    const int g = lane >> 2;
    const int t = lane & 3;

    uint32_t As_base = (uint32_t)__cvta_generic_to_shared(As);
    uint32_t Bs_base = (uint32_t)__cvta_generic_to_shared(Bs);

    const int rowA_loc = lane & 15;
    const int a_klo = lane >> 4;
    const int sxA = rowA_loc & 7;
    const int rowB_loc = (lane & 7) + ((lane >> 4) << 3);
    const int b_klo = (lane >> 3) & 1;
    const int sxB = rowB_loc & 7;

    const uint32_t baseA = As_base + (uint32_t)((warp_m * 64 + rowA_loc) << 7);
    const uint32_t baseB0 = Bs_base + (uint32_t)((warp_n * 32 + rowB_loc) << 7);
    const uint32_t baseB1 = baseB0 + (16 << 7);

#pragma unroll
    for (int ks = 0; ks < 4; ks++) {
        uint32_t colA = (uint32_t)(((2 * ks + a_klo) ^ sxA) << 4);
        uint32_t colB = (uint32_t)(((2 * ks + b_klo) ^ sxB) << 4);

        uint32_t b0[4], b1[4];
        ldsm_x4(b0[0], b0[1], b0[2], b0[3], baseB0 + colB);
        ldsm_x4(b1[0], b1[1], b1[2], b1[3], baseB1 + colB);

#pragma unroll
        for (int mt = 0; mt < 4; mt++) {
            uint32_t a[4];
            ldsm_x4(a[0], a[1], a[2], a[3], baseA + (uint32_t)(mt << 11) + colA);
            mma_f16(acc[mt][0], a, b0[0], b0[1]);
            mma_f16(acc[mt][1], a, b0[2], b0[3]);
            mma_f16(acc[mt][2], a, b1[0], b1[1]);
            mma_f16(acc[mt][3], a, b1[2], b1[3]);
        }
    }

    // ---- Epilogue ----
    float w2v[2][4];
#pragma unroll
    for (int ntp = 0; ntp < 2; ntp++)
#pragma unroll
        for (int q = 0; q < 4; q++) {
            int col = warp_n * 32 + ntp * 16 + 4 * t + q;
            w2v[ntp][q] = w2p[0][col] + w2p[1][col];
        }

    const int jbase = j0 + warp_n * 32 + 4 * t;

    if (j0 + TN <= K) {
        // Full tile: branch-free, 16 naked STG.128
#pragma unroll
        for (int mt = 0; mt < 4; mt++) {
            int R = warp_m * 64 + mt * 16 + g;
            float x2lo = x2s[R];
            float x2hi = x2s[R + 8];
            float* o0 = out + (long)(m0 + R) * K + jbase;
            float* o1 = out + (long)(m0 + R + 8) * K + jbase;
#pragma unroll
            for (int ntp = 0; ntp < 2; ntp++) {
                const float* aq0 = acc[mt][2 * ntp + 0];
                const float* aq1 = acc[mt][2 * ntp + 1];
                float4 lo, hi;
                lo.x = dist_val(x2lo + w2v[ntp][0], aq0[0]);
                lo.y = dist_val(x2lo + w2v[ntp][1], aq0[1]);
                lo.z = dist_val(x2lo + w2v[ntp][2], aq1[0]);
                lo.w = dist_val(x2lo + w2v[ntp][3], aq1[1]);
                hi.x = dist_val(x2hi + w2v[ntp][0], aq0[2]);
                hi.y = dist_val(x2hi + w2v[ntp][1], aq0[3]);
                hi.z = dist_val(x2hi + w2v[ntp][2], aq1[2]);
                hi.w = dist_val(x2hi + w2v[ntp][3], aq1[3]);
                *reinterpret_cast<float4*>(o0 + ntp * 16) = lo;
                *reinterpret_cast<float4*>(o1 + ntp * 16) = hi;
            }
        }
    } else {
        // Boundary tile: compact guarded scalar path
#pragma unroll
        for (int mt = 0; mt < 4; mt++) {
            int R = warp_m * 64 + mt * 16 + g;
            float x2lo = x2s[R];
            float x2hi = x2s[R + 8];
            long row0 = (long)(m0 + R) * K;
            long row1 = (long)(m0 + R + 8) * K;
            for (int ntp = 0; ntp < 2; ntp++) {
                const float* aq0 = acc[mt][2 * ntp + 0];
                const float* aq1 = acc[mt][2 * ntp + 1];
                for (int q = 0; q < 4; q++) {
                    int j = jbase + ntp * 16 + q;
                    if (j >= K) continue;
                    float a0 = (q < 2) ? aq0[q] : aq1[q - 2];
                    float a1 = (q < 2) ? aq0[q + 2] : aq1[q];
                    out[row0 + j] = dist_val(x2lo + w2v[ntp][q], a0);
                    out[row1 + j] = dist_val(x2hi + w2v[ntp][q], a1);
                }
            }
        }
    }
}

// ---------------------------------------------------------------------------
// Launch (single kernel)
// ---------------------------------------------------------------------------
extern "C" void kernel_launch(void* const* d_in, const int* in_sizes, int n_in,
                              void* d_out, int out_size) {
    const float* x = (const float*)d_in[0];   // [B, 64]
    const float* w = (const float*)d_in[1];   // [64, K]
    float* out = (float*)d_out;               // [B, K]

    int B = in_sizes[0] / DIM;
    int K = in_sizes[1] / DIM;

    dim3 grid((K + TN - 1) / TN, (B + TM - 1) / TM);
    dist_mma_kernel<<<grid, 256>>>(x, w, out, B, K);
}